// round 14
// baseline (speedup 1.0000x reference)
#include <cuda_runtime.h>
#include <math.h>

// SBEceLoss: logits [N,100] f32, labels [N] i64 -> scalar ece (f32)
// 4-deep TMA ring + DEEP L2 BULK PREFETCH (decouples DRAM->L2 from L2->SM):
//   - cp.async.bulk.prefetch.L2 streams tiles ~10 iterations ahead into L2
//     (no SMEM, no mbarrier) -> TMA fills become L2 hits (~234cyc)
//   - 32-row tiles (12.8KB); cp.async.bulk + mbarrier complete_tx per tile
//   - inner scan: LDS + FSETP + FSEL + SEL per element
//   - certification via merge intermediates: min(pairmax01, pairmax23) > -4
//     && -16 < m < 8  ->  acc == 0 proven exactly (fallback otherwise)
//   - per-block shared histogram -> global REDs
//   - last block computes 100x15 bin softmax + ECE, resets device state.

#define C_CLASSES 100
#define NB 15
#define TILE_ROWS 32
#define TILE_FLOATS (TILE_ROWS * C_CLASSES)   // 3200
#define TILE_BYTES  (TILE_FLOATS * 4)         // 12800
#define NBUF 4
#define PFDIST 10                              // prefetch distance (iterations)
#define THREADS 128
#define FULLM 0xffffffffu

__device__ int g_cnt[C_CLASSES];
__device__ int g_acc[C_CLASSES];
__device__ unsigned g_done;

__device__ __forceinline__ void mbar_init(unsigned mbar, unsigned count) {
    asm volatile("mbarrier.init.shared.b64 [%0], %1;" :: "r"(mbar), "r"(count) : "memory");
}
__device__ __forceinline__ void mbar_expect_tx(unsigned mbar, unsigned bytes) {
    asm volatile("mbarrier.arrive.expect_tx.shared.b64 _, [%0], %1;"
                 :: "r"(mbar), "r"(bytes) : "memory");
}
__device__ __forceinline__ void bulk_g2s(unsigned sdst, const void* gsrc,
                                         unsigned bytes, unsigned mbar) {
    asm volatile("cp.async.bulk.shared::cta.global.mbarrier::complete_tx::bytes "
                 "[%0], [%1], %2, [%3];"
                 :: "r"(sdst), "l"(gsrc), "r"(bytes), "r"(mbar) : "memory");
}
__device__ __forceinline__ void l2_prefetch(const void* gsrc, unsigned bytes) {
    asm volatile("cp.async.bulk.prefetch.L2.global [%0], %1;"
                 :: "l"(gsrc), "r"(bytes) : "memory");
}
__device__ __forceinline__ void mbar_wait(unsigned mbar, unsigned parity) {
    asm volatile(
        "{\n\t"
        ".reg .pred P;\n\t"
        "WAIT_%=:\n\t"
        "mbarrier.try_wait.parity.acquire.cta.shared::cta.b64 P, [%0], %1, 0x989680;\n\t"
        "@P bra.uni DONE_%=;\n\t"
        "bra.uni WAIT_%=;\n\t"
        "DONE_%=:\n\t"
        "}"
        :: "r"(mbar), "r"(parity) : "memory");
}

__global__ void __launch_bounds__(THREADS)
fused_kernel(const float* __restrict__ logits,
             const long long* __restrict__ labels,
             int n_rows, float* __restrict__ out) {
    extern __shared__ __align__(16) float sdyn[];            // NBUF * 3200 floats
    __shared__ __align__(8) unsigned long long mbar_st[NBUF];
    __shared__ int  s_cnt[C_CLASSES];
    __shared__ int  s_acc[C_CLASSES];
    __shared__ bool s_last;

    const int tid = threadIdx.x;
    for (int i = tid; i < C_CLASSES; i += THREADS) { s_cnt[i] = 0; s_acc[i] = 0; }

    unsigned mb[NBUF], sb[NBUF];
    #pragma unroll
    for (int i = 0; i < NBUF; i++) {
        mb[i] = (unsigned)__cvta_generic_to_shared(&mbar_st[i]);
        sb[i] = (unsigned)__cvta_generic_to_shared(&sdyn[i * TILE_FLOATS]);
    }
    if (tid == 0) {
        #pragma unroll
        for (int i = 0; i < NBUF; i++) mbar_init(mb[i], 1);
    }
    __syncthreads();   // mbarriers visible before any TMA targets them

    const int tiles = (n_rows + TILE_ROWS - 1) / TILE_ROWS;
    const int grid  = gridDim.x;

    // ---- prologue: TMA tiles k=0..NBUF-2; L2-prefetch tiles k=NBUF-1..PFDIST-1
    if (tid == 0) {
        #pragma unroll
        for (int k = 0; k < NBUF - 1; k++) {
            int t = blockIdx.x + k * grid;
            if (t < tiles) {
                unsigned bytes = (unsigned)(min(TILE_ROWS, n_rows - t * TILE_ROWS) * 400);
                mbar_expect_tx(mb[k], bytes);
                bulk_g2s(sb[k], (const char*)logits + (size_t)t * TILE_BYTES, bytes, mb[k]);
            }
        }
        for (int k = NBUF - 1; k < PFDIST; k++) {
            int t = blockIdx.x + k * grid;
            if (t < tiles) {
                unsigned bytes = (unsigned)(min(TILE_ROWS, n_rows - t * TILE_ROWS) * 400);
                l2_prefetch((const char*)logits + (size_t)t * TILE_BYTES, bytes);
            }
        }
    }

    const int q = tid & 3;               // quarter within the row
    int k = 0;
    for (int tile = blockIdx.x; tile < tiles; tile += grid, k++) {
        if (tid == 0) {
            // deep L2 prefetch: DRAM->L2 pump, no SMEM/barrier needed
            int pt = tile + PFDIST * grid;
            if (pt < tiles) {
                unsigned bytes = (unsigned)(min(TILE_ROWS, n_rows - pt * TILE_ROWS) * 400);
                l2_prefetch((const char*)logits + (size_t)pt * TILE_BYTES, bytes);
            }
            // TMA for iteration k+NBUF-1 (buffer consumed at iteration k-1;
            // that iteration's __syncthreads ordered all reads before refill)
            int nt = tile + (NBUF - 1) * grid;
            if (nt < tiles) {
                int nb = (k + NBUF - 1) & (NBUF - 1);
                unsigned bytes = (unsigned)(min(TILE_ROWS, n_rows - nt * TILE_ROWS) * 400);
                mbar_expect_tx(mb[nb], bytes);
                bulk_g2s(sb[nb], (const char*)logits + (size_t)nt * TILE_BYTES, bytes, mb[nb]);
            }
        }

        // wait for current tile: buffer k&3, phase parity (k>>2)&1
        const int b = k & (NBUF - 1);
        mbar_wait(mb[b], (k >> 2) & 1);

        // ---- thread-local quarter-row scan (conflict-free: stride 25) ----
        const float* rp = &sdyn[b * TILE_FLOATS + tid * 25];
        float m   = rp[0];
        int   idx = q * 25;
        #pragma unroll
        for (int i = 1; i < 25; i++) {
            float x = rp[i];
            bool p = x > m;                  // strict > keeps first occurrence
            m   = p ? x : m;
            idx = p ? q * 25 + i : idx;
        }

        // ---- merge 4 quarters: (value desc, index asc) + cert lower bound ----
        {
            float om = __shfl_xor_sync(FULLM, m,   1);
            int   oi = __shfl_xor_sync(FULLM, idx, 1);
            bool take = (om > m) || (om == m && oi < idx);
            m   = take ? om : m;
            idx = take ? oi : idx;
        }
        float second_lb;
        {
            float om = __shfl_xor_sync(FULLM, m,   2);
            int   oi = __shfl_xor_sync(FULLM, idx, 2);
            second_lb = fminf(m, om);   // a REAL element distinct from the argmax
            bool take = (om > m) || (om == m && oi < idx);
            m   = take ? om : m;
            idx = take ? oi : idx;
        }

        int row = tile * TILE_ROWS + (tid >> 2);
        if (q == 0 && row < n_rows) {
            // cert: 2nd element > -4 > m-12 (since m < 8) and |m| < 16 =>
            // log(sumexp) >= log(1+e^-12) = 6.1e-6 > ulp(16)/2 => max logprob
            // strictly < 0 => never equals an integer label => acc = 0.
            bool good = (second_lb > -4.0f) && (m < 8.0f) && (m > -16.0f);
            if (!good) {   // statistically never taken
                const float* rb = &sdyn[b * TILE_FLOATS + (tid >> 2) * C_CLASSES];
                float sv = 0.0f;
                for (int i = 0; i < C_CLASSES; i++) sv += expf(rb[i] - m);
                float pred = m - (m + logf(sv));
                if (pred == (float)labels[row]) atomicAdd(&s_acc[idx], 1);
            }
            atomicAdd(&s_cnt[idx], 1);
        }
        __syncthreads();   // all reads of buf b done before it is re-filled
    }

    // ---- flush block histogram to global ----
    for (int i = tid; i < C_CLASSES; i += THREADS) {
        int c = s_cnt[i]; if (c) atomicAdd(&g_cnt[i], c);
        int a = s_acc[i]; if (a) atomicAdd(&g_acc[i], a);
    }
    __threadfence();
    __syncthreads();

    if (tid == 0) {
        unsigned rank = atomicAdd(&g_done, 1u);
        s_last = (rank == gridDim.x - 1);
    }
    __syncthreads();
    if (!s_last) return;

    // ================= finalize (last block only; alias dynamic SMEM) ======
    float (*s_coef)[NB + 1] = reinterpret_cast<float(*)[NB + 1]>(&sdyn[0]);  // 1600 f
    int*   s_c2   = reinterpret_cast<int*>(&sdyn[1600]);
    int*   s_a2   = reinterpret_cast<int*>(&sdyn[1728]);
    float* s_sum  = &sdyn[1856];
    float* s_conf = &sdyn[1872];
    float* s_accs = &sdyn[1888];

    int t = tid;
    if (t < C_CLASSES) {
        int cnt = __ldcg(&g_cnt[t]);
        int ac  = __ldcg(&g_acc[t]);
        s_c2[t] = cnt;
        s_a2[t] = ac;
        float cf = (float)t;
        float d[NB];
        float dmax = __int_as_float(0xff800000);
        #pragma unroll
        for (int jj = 0; jj < NB; jj++) {
            float aj = (float)((2 * jj + 1) / 30.0);
            float tt = cf - aj;
            d[jj] = -(tt * tt) / 0.01f;
            dmax = fmaxf(dmax, d[jj]);
        }
        float denom = 0.0f;
        #pragma unroll
        for (int jj = 0; jj < NB; jj++) denom += expf(d[jj] - dmax);
        #pragma unroll
        for (int jj = 0; jj < NB; jj++) s_coef[t][jj] = expf(d[jj] - dmax) / denom;
        g_cnt[t] = 0;     // reset for next graph replay
        g_acc[t] = 0;
    }
    if (t == 0) g_done = 0;
    __syncthreads();

    if (t < NB) {
        float sum_c = 0.0f, sum_cc = 0.0f, sum_a = 0.0f;
        for (int c = 0; c < C_CLASSES; c++) {
            int cnt = s_c2[c];
            int ac  = s_a2[c];
            if ((cnt | ac) == 0) continue;
            float coeff = s_coef[c][t];
            float fcnt  = (float)cnt;   // exact: cnt < 2^24
            float cf    = (float)c;
            sum_c  += fcnt * coeff;
            sum_cc += fcnt * cf * coeff;
            sum_a  += (float)ac * coeff;
        }
        s_sum[t]  = sum_c;
        s_conf[t] = sum_cc;
        s_accs[t] = sum_a;
    }
    __syncthreads();

    if (t == 0) {
        float tot = 0.0f;
        #pragma unroll
        for (int jj = 0; jj < NB; jj++) tot += fabsf(s_sum[jj]);
        float wden = fmaxf(tot, 1e-5f);
        float acc2 = 0.0f;
        #pragma unroll
        for (int jj = 0; jj < NB; jj++) {
            float den = fmaxf(s_sum[jj], 1e-5f);
            float bc  = s_conf[jj] / den;
            float ba  = s_accs[jj] / den;
            float w   = s_sum[jj] / wden;
            float df  = bc - ba;
            acc2 += df * df * w;
        }
        out[0] = sqrtf(acc2);
    }
}

extern "C" void kernel_launch(void* const* d_in, const int* in_sizes, int n_in,
                              void* d_out, int out_size) {
    const float*     logits = (const float*)d_in[0];
    const long long* labels = (const long long*)d_in[1];
    float*           out    = (float*)d_out;
    int n_rows = in_sizes[1];  // labels count = N

    const int smem_bytes = NBUF * TILE_BYTES;  // 51200
    cudaFuncSetAttribute(fused_kernel,
                         cudaFuncAttributeMaxDynamicSharedMemorySize, smem_bytes);
    // 592 = 4 blocks/SM * 148 SMs, single wave
    fused_kernel<<<592, THREADS, smem_bytes>>>(logits, labels, n_rows, out);
}

// round 15
// speedup vs baseline: 1.2296x; 1.2296x over previous
#include <cuda_runtime.h>
#include <math.h>

// SBEceLoss: logits [N,100] f32, labels [N] i64 -> scalar ece (f32)
// Champion structure (R10) + contiguous per-block streams + hoisted coef table.
//   - each block owns a CONTIGUOUS span of tiles (HBM row-buffer locality)
//   - 32-row tiles (12.8KB) double-buffered via cp.async.cg (16B, coalesced)
//   - inner scan: LDS + FSETP + FSEL + SEL per element
//   - certification via merge intermediates: min(pairmax01, pairmax23) > -4
//     && -16 < m < 8  ->  acc == 0 proven exactly (fallback otherwise)
//   - block 0 precomputes the 100x15 bin-softmax coef table at START
//     (overlapped with streaming); last block's finalize just reads it
//   - per-block shared histogram -> global REDs; last block -> ECE + reset.

#define C_CLASSES 100
#define NB 15
#define TILE_ROWS 32
#define TILE_FLOATS (TILE_ROWS * C_CLASSES)   // 3200
#define TILE_BYTES  (TILE_FLOATS * 4)         // 12800
#define THREADS 128
#define FULLM 0xffffffffu

__device__ int   g_cnt[C_CLASSES];
__device__ int   g_acc[C_CLASSES];
__device__ float g_coef[C_CLASSES][NB];
__device__ unsigned g_done;

__device__ __forceinline__ void cp_async16(unsigned saddr, const void* gaddr) {
    asm volatile("cp.async.cg.shared.global [%0], [%1], 16;" :: "r"(saddr), "l"(gaddr));
}
__device__ __forceinline__ void cp_commit() {
    asm volatile("cp.async.commit_group;" ::: "memory");
}

__global__ void __launch_bounds__(THREADS)
fused_kernel(const float* __restrict__ logits,
             const long long* __restrict__ labels,
             int n_rows, float* __restrict__ out) {
    __shared__ __align__(16) float sbuf[2][TILE_FLOATS];   // 25.6 KB
    __shared__ int  s_cnt[C_CLASSES];
    __shared__ int  s_acc[C_CLASSES];
    __shared__ bool s_last;

    const int tid = threadIdx.x;
    for (int i = tid; i < C_CLASSES; i += THREADS) { s_cnt[i] = 0; s_acc[i] = 0; }

    const int tiles = (n_rows + TILE_ROWS - 1) / TILE_ROWS;
    const int tpb   = (tiles + gridDim.x - 1) / gridDim.x;   // tiles per block
    const int t0    = blockIdx.x * tpb;                      // contiguous span
    const int t1    = min(t0 + tpb, tiles);

    const unsigned sb[2] = {
        (unsigned)__cvta_generic_to_shared(&sbuf[0][0]),
        (unsigned)__cvta_generic_to_shared(&sbuf[1][0])
    };

    // ---- prologue prefetch (first owned tile into buffer 0) ----
    if (t0 < t1) {
        const char* g = (const char*)logits + (size_t)t0 * TILE_BYTES;
        int valid = min(TILE_ROWS, n_rows - t0 * TILE_ROWS) * 400;
        #pragma unroll
        for (int k = 0; k < 7; k++) {
            int off = (tid + k * THREADS) * 16;
            if (off < TILE_BYTES && off < valid) cp_async16(sb[0] + off, g + off);
        }
    }
    cp_commit();

    // ---- block 0: precompute bin-softmax coef table (overlaps streaming) ----
    // Ordered before finalize readers by the __threadfence preceding g_done.
    if (blockIdx.x == 0 && tid < C_CLASSES) {
        float cf = (float)tid;
        float d[NB];
        float dmax = __int_as_float(0xff800000);
        #pragma unroll
        for (int jj = 0; jj < NB; jj++) {
            float aj = (float)((2 * jj + 1) / 30.0);
            float tt = cf - aj;
            d[jj] = -(tt * tt) / 0.01f;
            dmax = fmaxf(dmax, d[jj]);
        }
        float denom = 0.0f;
        #pragma unroll
        for (int jj = 0; jj < NB; jj++) denom += expf(d[jj] - dmax);
        #pragma unroll
        for (int jj = 0; jj < NB; jj++) g_coef[tid][jj] = expf(d[jj] - dmax) / denom;
    }

    const int q = tid & 3;               // quarter within the row
    int b = 0;
    for (int tile = t0; tile < t1; tile++, b ^= 1) {
        // issue next tile into the other buffer (overlaps current processing)
        int next = tile + 1;
        if (next < t1) {
            const char* g = (const char*)logits + (size_t)next * TILE_BYTES;
            int valid = min(TILE_ROWS, n_rows - next * TILE_ROWS) * 400;
            unsigned sdst = sb[b ^ 1];
            #pragma unroll
            for (int k = 0; k < 7; k++) {
                int off = (tid + k * THREADS) * 16;
                if (off < TILE_BYTES && off < valid) cp_async16(sdst + off, g + off);
            }
        }
        cp_commit();
        asm volatile("cp.async.wait_group 1;" ::: "memory");  // current tile ready
        __syncthreads();

        // ---- thread-local quarter-row scan (conflict-free: stride 25) ----
        const float* rp = &sbuf[b][tid * 25];
        float m   = rp[0];
        int   idx = q * 25;
        #pragma unroll
        for (int i = 1; i < 25; i++) {
            float x = rp[i];
            bool p = x > m;                  // strict > keeps first occurrence
            m   = p ? x : m;
            idx = p ? q * 25 + i : idx;
        }

        // ---- merge 4 quarters: (value desc, index asc) + cert lower bound ----
        {
            float om = __shfl_xor_sync(FULLM, m,   1);
            int   oi = __shfl_xor_sync(FULLM, idx, 1);
            bool take = (om > m) || (om == m && oi < idx);
            m   = take ? om : m;
            idx = take ? oi : idx;
        }
        float second_lb;
        {
            float om = __shfl_xor_sync(FULLM, m,   2);
            int   oi = __shfl_xor_sync(FULLM, idx, 2);
            second_lb = fminf(m, om);   // a REAL element distinct from the argmax
            bool take = (om > m) || (om == m && oi < idx);
            m   = take ? om : m;
            idx = take ? oi : idx;
        }

        int row = tile * TILE_ROWS + (tid >> 2);
        if (q == 0 && row < n_rows) {
            // cert: 2nd element > -4 > m-12 (since m < 8) and |m| < 16 =>
            // log(sumexp) >= log(1+e^-12) = 6.1e-6 > ulp(16)/2 => max logprob
            // strictly < 0 => never equals an integer label => acc = 0.
            bool good = (second_lb > -4.0f) && (m < 8.0f) && (m > -16.0f);
            if (!good) {   // statistically never taken
                const float* rb = &sbuf[b][(tid >> 2) * C_CLASSES];
                float sv = 0.0f;
                for (int i = 0; i < C_CLASSES; i++) sv += expf(rb[i] - m);
                float pred = m - (m + logf(sv));
                if (pred == (float)labels[row]) atomicAdd(&s_acc[idx], 1);
            }
            atomicAdd(&s_cnt[idx], 1);
        }
        __syncthreads();   // all reads of buf b done before it is re-filled
    }
    asm volatile("cp.async.wait_group 0;" ::: "memory");

    // ---- flush block histogram to global ----
    __syncthreads();
    for (int i = tid; i < C_CLASSES; i += THREADS) {
        int c = s_cnt[i]; if (c) atomicAdd(&g_cnt[i], c);
        int a = s_acc[i]; if (a) atomicAdd(&g_acc[i], a);
    }
    __threadfence();     // orders histogram REDs AND block 0's g_coef stores
    __syncthreads();

    if (tid == 0) {
        unsigned rank = atomicAdd(&g_done, 1u);
        s_last = (rank == gridDim.x - 1);
    }
    __syncthreads();
    if (!s_last) return;

    // ================= finalize (last block only; alias tile SMEM) =========
    float (*s_coef)[NB + 1] = reinterpret_cast<float(*)[NB + 1]>(&sbuf[0][0]); // 1600 f
    int*   s_c2   = reinterpret_cast<int*>(&sbuf[0][1600]);
    int*   s_a2   = reinterpret_cast<int*>(&sbuf[0][1728]);
    float* s_sum  = &sbuf[0][1856];
    float* s_conf = &sbuf[0][1872];
    float* s_accs = &sbuf[0][1888];

    int t = tid;
    if (t < C_CLASSES) {
        s_c2[t] = __ldcg(&g_cnt[t]);
        s_a2[t] = __ldcg(&g_acc[t]);
        #pragma unroll
        for (int jj = 0; jj < NB; jj++) s_coef[t][jj] = __ldcg(&g_coef[t][jj]);
        g_cnt[t] = 0;     // reset for next graph replay
        g_acc[t] = 0;
    }
    if (t == 0) g_done = 0;
    __syncthreads();

    if (t < NB) {
        float sum_c = 0.0f, sum_cc = 0.0f, sum_a = 0.0f;
        for (int c = 0; c < C_CLASSES; c++) {
            int cnt = s_c2[c];
            int ac  = s_a2[c];
            if ((cnt | ac) == 0) continue;
            float coeff = s_coef[c][t];
            float fcnt  = (float)cnt;   // exact: cnt < 2^24
            float cf    = (float)c;
            sum_c  += fcnt * coeff;
            sum_cc += fcnt * cf * coeff;
            sum_a  += (float)ac * coeff;
        }
        s_sum[t]  = sum_c;
        s_conf[t] = sum_cc;
        s_accs[t] = sum_a;
    }
    __syncthreads();

    if (t == 0) {
        float tot = 0.0f;
        #pragma unroll
        for (int jj = 0; jj < NB; jj++) tot += fabsf(s_sum[jj]);
        float wden = fmaxf(tot, 1e-5f);
        float acc2 = 0.0f;
        #pragma unroll
        for (int jj = 0; jj < NB; jj++) {
            float den = fmaxf(s_sum[jj], 1e-5f);
            float bc  = s_conf[jj] / den;
            float ba  = s_accs[jj] / den;
            float w   = s_sum[jj] / wden;
            float df  = bc - ba;
            acc2 += df * df * w;
        }
        out[0] = sqrtf(acc2);
    }
}

extern "C" void kernel_launch(void* const* d_in, const int* in_sizes, int n_in,
                              void* d_out, int out_size) {
    const float*     logits = (const float*)d_in[0];
    const long long* labels = (const long long*)d_in[1];
    float*           out    = (float*)d_out;
    int n_rows = in_sizes[1];  // labels count = N

    // 16384 tiles / 1024 blocks = 16 contiguous tiles per block (204.8 KB span)
    fused_kernel<<<1024, THREADS>>>(logits, labels, n_rows, out);
}